// round 7
// baseline (speedup 1.0000x reference)
#include <cuda_runtime.h>

// EMEncoder_21483426414987 — masked per-label means + overall masked mean.
// tarsent_state [8,512,512] f32, tar_func [8,512] i32,
// refsent_state [8,32,256,512] f32, ref_func [8,32,256] i32.
// Output flat f32: tar_aug[8,5,512], tar_aug_mask[8,5], ref_aug[8,32,5,512],
// ref_aug_mask[8,32,5], tarpaper[8,512], tar_mask2[8], refpaper[8,32,512],
// ref_mask2[8,32]. Total 812592 floats. Masks as 1.0/0.0.
//
// R5: per-label sentence index lists (built deterministically by warp 0 via
// ballot/popc ranking), then 5 tight gather loops with register accumulators.
// No smem RMW in the hot loop, no branches, dual partial accumulators for MLP.
// tar = 8 tiles x 8 chunks of 16 cols; ref = 256 tiles x 4 chunks of 32 cols.

#define H    512
#define HQ   128    // H/4 float4 per row
#define NLAB 5

#define OFF_TAR_AUG   0
#define OFF_TAR_AMSK  20480
#define OFF_REF_AUG   20520
#define OFF_REF_AMSK  675880
#define OFF_TAR_PAP   677160
#define OFF_TAR_PMSK  681256
#define OFF_REF_PAP   681264
#define OFF_REF_PMSK  812336

__device__ __forceinline__ void f4add(float4& a, const float4& v) {
    a.x += v.x; a.y += v.y; a.z += v.z; a.w += v.w;
}

__global__ __launch_bounds__(256, 8) void em_reduce_kernel(
    const float* __restrict__ tar_state, const int* __restrict__ tar_func,
    const float* __restrict__ ref_state, const int* __restrict__ ref_func,
    float* __restrict__ out)
{
    __shared__ float4 spart[NLAB * 256];  // [label][tid] partial sums
    __shared__ short  sidx[512];          // label-sorted sentence indices
    __shared__ int    soff[NLAB + 1];     // label segment offsets

    const int bid = blockIdx.x;
    const float4* state;
    const int*    func;
    int S, chunk, wsh;        // wsh: log2(subgroup width)
    long aug_off, pap_off;
    int  amsk_off, pmsk_off;

    if (bid < 64) {                       // tar: 8 tiles x 8 chunks (Wc=16)
        const int b = bid >> 3;
        chunk    = bid & 7;
        wsh      = 4;
        S        = 512;
        state    = (const float4*)(tar_state + (size_t)b * 512 * H);
        func     = tar_func + b * 512;
        aug_off  = OFF_TAR_AUG + (long)b * NLAB * H;
        amsk_off = OFF_TAR_AMSK + b * NLAB;
        pap_off  = OFF_TAR_PAP + (long)b * H;
        pmsk_off = OFF_TAR_PMSK + b;
    } else {                              // ref: 256 tiles x 4 chunks (Wc=32)
        const int r   = bid - 64;
        const int idx = r >> 2;           // b*32 + d
        chunk    = r & 3;
        wsh      = 5;
        S        = 256;
        state    = (const float4*)(ref_state + (size_t)idx * 256 * H);
        func     = ref_func + idx * 256;
        aug_off  = OFF_REF_AUG + (long)idx * NLAB * H;
        amsk_off = OFF_REF_AMSK + idx * NLAB;
        pap_off  = OFF_REF_PAP + (long)idx * H;
        pmsk_off = OFF_REF_PMSK + idx;
    }

    const int tid  = threadIdx.x;
    const int Wc   = 1 << wsh;            // subgroup width (cols)
    const int NS   = 256 >> wsh;          // #subgroups
    const int colw = tid & (Wc - 1);
    const int sub  = tid >> wsh;
    const int hq   = chunk * Wc + colw;   // global float4 column

    // ---- warp 0 builds label-sorted index lists (deterministic) ----
    if (tid < 32) {
        const int nch = S >> 5;
        const unsigned lt = (1u << tid) - 1u;

        int cnt[NLAB] = {0, 0, 0, 0, 0};
        for (int c = 0; c < nch; c++) {
            int f = func[c * 32 + tid];
            #pragma unroll
            for (int l = 1; l <= NLAB; l++) {
                unsigned m = __ballot_sync(0xffffffffu, f == l);
                cnt[l - 1] += __popc(m);
            }
        }
        // identical cnt in every lane -> offsets
        int offs[NLAB + 1];
        offs[0] = 0;
        #pragma unroll
        for (int l = 0; l < NLAB; l++) offs[l + 1] = offs[l] + cnt[l];
        if (tid <= NLAB) soff[tid] = offs[tid];

        int cur[NLAB] = {0, 0, 0, 0, 0};
        for (int c = 0; c < nch; c++) {
            int s = c * 32 + tid;
            int f = func[s];
            #pragma unroll
            for (int l = 1; l <= NLAB; l++) {
                unsigned m = __ballot_sync(0xffffffffu, f == l);
                if (f == l)
                    sidx[offs[l - 1] + cur[l - 1] + __popc(m & lt)] = (short)s;
                cur[l - 1] += __popc(m);
            }
        }
    }
    __syncthreads();

    // ---- 5 gather loops: one register accumulator pair per label ----
    const float4 z = make_float4(0.f, 0.f, 0.f, 0.f);
    #pragma unroll
    for (int l = 0; l < NLAB; l++) {
        const int lo = soff[l];
        const int n  = soff[l + 1] - lo;
        float4 aA = z, aB = z;
        int j = sub;
        for (; j + NS < n; j += 2 * NS) {
            const int sA = sidx[lo + j];
            const int sB = sidx[lo + j + NS];
            float4 vA = __ldg(&state[(size_t)sA * HQ + hq]);
            float4 vB = __ldg(&state[(size_t)sB * HQ + hq]);
            f4add(aA, vA);
            f4add(aB, vB);
        }
        if (j < n) {
            const int sA = sidx[lo + j];
            f4add(aA, __ldg(&state[(size_t)sA * HQ + hq]));
        }
        f4add(aA, aB);
        spart[l * 256 + tid] = aA;        // sub*Wc + colw == tid & 255
    }
    __syncthreads();

    // ---- epilogue: warp l reduces label l; warp 5 paper mean; masks ----
    const int wid  = tid >> 5;
    const int lane = tid & 31;
    float4* out4 = (float4*)out;
    const long aug4 = aug_off >> 2;
    const long pap4 = pap_off >> 2;

    if (wid < NLAB) {
        if (lane < Wc) {
            float4 ssum = z;
            for (int p = 0; p < NS; p++)
                f4add(ssum, spart[wid * 256 + p * Wc + lane]);
            const int cnt = soff[wid + 1] - soff[wid];
            float4 r = z;
            if (cnt > 0) {
                float inv = 1.0f / (float)cnt;
                r = make_float4(ssum.x*inv, ssum.y*inv, ssum.z*inv, ssum.w*inv);
            }
            out4[aug4 + (long)wid * HQ + chunk * Wc + lane] = r;
        }
    } else if (wid == 5) {
        if (lane < Wc) {
            float4 ssum = z;
            for (int l = 0; l < NLAB; l++)
                for (int p = 0; p < NS; p++)
                    f4add(ssum, spart[l * 256 + p * Wc + lane]);
            const int ct = soff[NLAB];            // total non-pad count
            float4 r = z;
            if (ct > 0) {
                float inv = 1.0f / (float)ct;
                r = make_float4(ssum.x*inv, ssum.y*inv, ssum.z*inv, ssum.w*inv);
            }
            out4[pap4 + chunk * Wc + lane] = r;
        }
    } else if (wid == 6 && lane == 0 && chunk == 0) {
        #pragma unroll
        for (int l = 0; l < NLAB; l++)
            out[amsk_off + l] = (soff[l + 1] - soff[l] > 0) ? 1.0f : 0.0f;
        out[pmsk_off] = (soff[NLAB] > 0) ? 1.0f : 0.0f;
    }
}

extern "C" void kernel_launch(void* const* d_in, const int* in_sizes, int n_in,
                              void* d_out, int out_size) {
    const float* tar_state = (const float*)d_in[0];
    const int*   tar_func  = (const int*)d_in[1];
    const float* ref_state = (const float*)d_in[2];
    const int*   ref_func  = (const int*)d_in[3];
    float* out = (float*)d_out;

    // 8 tar tiles x 8 chunks + 256 ref tiles x 4 chunks = 1088 equal blocks
    em_reduce_kernel<<<64 + 1024, 256>>>(tar_state, tar_func,
                                         ref_state, ref_func, out);
}

// round 9
// speedup vs baseline: 1.2119x; 1.2119x over previous
#include <cuda_runtime.h>

// EMEncoder_21483426414987 — masked per-label means + overall masked mean.
// tarsent_state [8,512,512] f32, tar_func [8,512] i32,
// refsent_state [8,32,256,512] f32, ref_func [8,32,256] i32.
// Output flat f32 concat (total 812592 floats), masks as 1.0/0.0.
//
// R6 = R4 + branch-free hot loop:
//   * predicated LDG (inline PTX @p ld.global.nc.v4) — no BSSY/BSYNC between
//     loads, pad rows still skipped in DRAM
//   * always-RMW into 6-slot smem accumulator (slot 0 = trash for f==0)
//   * labels packed 4-per-word in smem: 1 LDS per 4 iterations
// Equal blocks: tar = 8 tiles x 8 chunks (Wc=16, NS=16), ref = 256 tiles x
// 4 chunks (Wc=32, NS=8); every block = 32 iterations = 8 batches of 4.

#define H    512
#define HQ   128    // H/4 float4 per row
#define NLAB 5

#define OFF_TAR_AUG   0
#define OFF_TAR_AMSK  20480
#define OFF_REF_AUG   20520
#define OFF_REF_AMSK  675880
#define OFF_TAR_PAP   677160
#define OFF_TAR_PMSK  681256
#define OFF_REF_PAP   681264
#define OFF_REF_PMSK  812336

__device__ __forceinline__ void f4add(float4& a, const float4& v) {
    a.x += v.x; a.y += v.y; a.z += v.z; a.w += v.w;
}

// Branch-free predicated vector load: returns zeros when f == 0.
__device__ __forceinline__ float4 ldg_pred(const float4* p, int f) {
    float4 v = make_float4(0.f, 0.f, 0.f, 0.f);
    asm("{ .reg .pred p0; setp.ne.s32 p0, %4, 0;\n\t"
        "  @p0 ld.global.nc.v4.f32 {%0,%1,%2,%3}, [%5]; }"
        : "+f"(v.x), "+f"(v.y), "+f"(v.z), "+f"(v.w)
        : "r"(f), "l"(p));
    return v;
}

__global__ __launch_bounds__(256, 6) void em_reduce_kernel(
    const float* __restrict__ tar_state, const int* __restrict__ tar_func,
    const float* __restrict__ ref_state, const int* __restrict__ ref_func,
    float* __restrict__ out)
{
    __shared__ float4       sacc[6 * 256];   // slot 0 = trash, slots 1..5 = labels
    __shared__ unsigned int spack[128];      // packed labels: 4 per word
    __shared__ int          scnt[NLAB];

    const int bid = blockIdx.x;
    const float4* state;
    const int*    func;
    int S, chunk, wsh;
    long aug_off, pap_off;
    int  amsk_off, pmsk_off;

    if (bid < 64) {                       // tar: 8 tiles x 8 chunks (Wc=16)
        const int b = bid >> 3;
        chunk    = bid & 7;
        wsh      = 4;
        S        = 512;
        state    = (const float4*)(tar_state + (size_t)b * 512 * H);
        func     = tar_func + b * 512;
        aug_off  = OFF_TAR_AUG + (long)b * NLAB * H;
        amsk_off = OFF_TAR_AMSK + b * NLAB;
        pap_off  = OFF_TAR_PAP + (long)b * H;
        pmsk_off = OFF_TAR_PMSK + b;
    } else {                              // ref: 256 tiles x 4 chunks (Wc=32)
        const int r   = bid - 64;
        const int idx = r >> 2;           // b*32 + d
        chunk    = r & 3;
        wsh      = 5;
        S        = 256;
        state    = (const float4*)(ref_state + (size_t)idx * 256 * H);
        func     = ref_func + idx * 256;
        aug_off  = OFF_REF_AUG + (long)idx * NLAB * H;
        amsk_off = OFF_REF_AMSK + idx * NLAB;
        pap_off  = OFF_REF_PAP + (long)idx * H;
        pmsk_off = OFF_REF_PMSK + idx;
    }

    const int tid    = threadIdx.x;
    const int Wc     = 1 << wsh;          // subgroup width (cols)
    const int NS     = 256 >> wsh;        // #subgroups
    const int nshift = 8 - wsh;           // log2(NS)
    const int colw   = tid & (Wc - 1);
    const int sub    = tid >> wsh;
    const int hq     = chunk * Wc + colw; // global float4 column

    // zero accumulators (incl. trash slot) + counters
    const float4 z = make_float4(0.f, 0.f, 0.f, 0.f);
    #pragma unroll
    for (int i = 0; i < 6; i++) sacc[i * 256 + tid] = z;
    if (tid < NLAB) scnt[tid] = 0;
    if (tid < 128)  spack[tid] = 0;

    __syncthreads();

    // stage packed labels + cooperative counts
    {
        unsigned char* cSp = (unsigned char*)spack;
        int l1 = 0, l2 = 0, l3 = 0, l4 = 0, l5 = 0;
        for (int s = tid; s < S; s += 256) {
            int f = func[s];
            cSp[((s & (NS - 1)) << 5) + (s >> nshift)] = (unsigned char)f;
            l1 += (f == 1); l2 += (f == 2); l3 += (f == 3);
            l4 += (f == 4); l5 += (f == 5);
        }
        if (l1) atomicAdd(&scnt[0], l1);
        if (l2) atomicAdd(&scnt[1], l2);
        if (l3) atomicAdd(&scnt[2], l3);
        if (l4) atomicAdd(&scnt[3], l4);
        if (l5) atomicAdd(&scnt[4], l5);
    }
    __syncthreads();

    // ---- hot loop: 8 batches of 4 sentences, fully branch-free ----
    const size_t kstep = (size_t)NS * HQ;          // float4 stride per k
    #pragma unroll 2
    for (int b = 0; b < 8; b++) {
        const unsigned int w = spack[sub * 8 + b]; // 4 labels, one LDS
        const int f0 =  w        & 0xff;
        const int f1 = (w >>  8) & 0xff;
        const int f2 = (w >> 16) & 0xff;
        const int f3 = (w >> 24) & 0xff;

        const float4* pb = state + ((size_t)(sub + (b << 2) * NS) * HQ + hq);
        float4 v0 = ldg_pred(pb,             f0);
        float4 v1 = ldg_pred(pb + kstep,     f1);
        float4 v2 = ldg_pred(pb + 2 * kstep, f2);
        float4 v3 = ldg_pred(pb + 3 * kstep, f3);

        // always-RMW (slot f, slot 0 is trash; v == 0 there)
        float4 o0 = sacc[f0 * 256 + tid]; f4add(o0, v0); sacc[f0 * 256 + tid] = o0;
        float4 o1 = sacc[f1 * 256 + tid]; f4add(o1, v1); sacc[f1 * 256 + tid] = o1;
        float4 o2 = sacc[f2 * 256 + tid]; f4add(o2, v2); sacc[f2 * 256 + tid] = o2;
        float4 o3 = sacc[f3 * 256 + tid]; f4add(o3, v3); sacc[f3 * 256 + tid] = o3;
    }
    __syncthreads();

    // ---- epilogue: warp l reduces label l+1; warp 5 paper mean; masks ----
    const int wid  = tid >> 5;
    const int lane = tid & 31;
    float4* out4 = (float4*)out;
    const long aug4 = aug_off >> 2;
    const long pap4 = pap_off >> 2;

    if (wid < NLAB) {
        if (lane < Wc) {
            float4 ssum = z;
            for (int p = 0; p < NS; p++)
                f4add(ssum, sacc[(wid + 1) * 256 + p * Wc + lane]);
            const int cnt = scnt[wid];
            float4 r = z;
            if (cnt > 0) {
                float inv = 1.0f / (float)cnt;
                r = make_float4(ssum.x*inv, ssum.y*inv, ssum.z*inv, ssum.w*inv);
            }
            out4[aug4 + (long)wid * HQ + chunk * Wc + lane] = r;
        }
    } else if (wid == 5) {
        if (lane < Wc) {
            float4 ssum = z;
            for (int l = 1; l <= NLAB; l++)
                for (int p = 0; p < NS; p++)
                    f4add(ssum, sacc[l * 256 + p * Wc + lane]);
            const int ct = scnt[0] + scnt[1] + scnt[2] + scnt[3] + scnt[4];
            float4 r = z;
            if (ct > 0) {
                float inv = 1.0f / (float)ct;
                r = make_float4(ssum.x*inv, ssum.y*inv, ssum.z*inv, ssum.w*inv);
            }
            out4[pap4 + chunk * Wc + lane] = r;
        }
    } else if (wid == 6 && lane == 0 && chunk == 0) {
        const int c1 = scnt[0], c2 = scnt[1], c3 = scnt[2];
        const int c4 = scnt[3], c5 = scnt[4];
        out[amsk_off + 0] = (c1 > 0) ? 1.0f : 0.0f;
        out[amsk_off + 1] = (c2 > 0) ? 1.0f : 0.0f;
        out[amsk_off + 2] = (c3 > 0) ? 1.0f : 0.0f;
        out[amsk_off + 3] = (c4 > 0) ? 1.0f : 0.0f;
        out[amsk_off + 4] = (c5 > 0) ? 1.0f : 0.0f;
        out[pmsk_off] = ((c1 + c2 + c3 + c4 + c5) > 0) ? 1.0f : 0.0f;
    }
}

extern "C" void kernel_launch(void* const* d_in, const int* in_sizes, int n_in,
                              void* d_out, int out_size) {
    const float* tar_state = (const float*)d_in[0];
    const int*   tar_func  = (const int*)d_in[1];
    const float* ref_state = (const float*)d_in[2];
    const int*   ref_func  = (const int*)d_in[3];
    float* out = (float*)d_out;

    // 8 tar tiles x 8 chunks + 256 ref tiles x 4 chunks = 1088 equal blocks
    em_reduce_kernel<<<64 + 1024, 256>>>(tar_state, tar_func,
                                         ref_state, ref_func, out);
}